// round 12
// baseline (speedup 1.0000x reference)
#include <cuda_runtime.h>
#include <cuda_bf16.h>
#include <math.h>
#include <stdint.h>

// Problem constants
#define B  32768
#define K  8192
#define D  1024
#define DECAY   0.99f
#define ONE_M_D 0.01f
#define EPS     1e-5f
#define COMMIT  0.25f
#define NORM_EPS 1e-12f

// Candidate machinery
#define CAP    64
#define MARGIN 0.15f

// Output layout (flattened tuple, float32)
#define OFF_ZQ   0
#define OFF_IDS  (B*D)
#define OFF_LOSS (OFF_IDS + B)
#define OFF_CB   (OFF_LOSS + 1)              // odd -> no float4 stores
#define OFF_CNT  (OFF_CB + K*D)
#define OFF_W    (OFF_CNT + K)               // odd -> no float4 stores

// -------------------- device scratch (no allocation allowed) ----------------
__device__ __align__(16) __nv_bfloat16 g_a0[(size_t)B * D];   // bf16(z)
__device__ __align__(16) __nv_bfloat16 g_b0[(size_t)K * D];   // bf16(cb_norm)
__device__ __align__(16) float g_cbn[(size_t)K * D];          // fp32 cb_norm
__device__ __align__(16) float g_wsum[K * D];
__device__ int   g_cand[(size_t)B * CAP];
__device__ int   g_ccnt[B];
__device__ float g_cnt[K];
__device__ float g_ncnt[K];
__device__ float g_loss;

// -------------------- PTX helpers (compute_103-safe) ------------------------
__device__ __forceinline__ uint32_t smem_u32(const void* p) {
    uint32_t a;
    asm("{ .reg .u64 t; cvta.to.shared.u64 t, %1; cvt.u32.u64 %0, t; }"
        : "=r"(a) : "l"(p));
    return a;
}
__device__ __forceinline__ void cp_async16(uint32_t dst, const void* src) {
    asm volatile("cp.async.cg.shared.global [%0], [%1], 16;"
                 :: "r"(dst), "l"(src) : "memory");
}
__device__ __forceinline__ void cp_commit() {
    asm volatile("cp.async.commit_group;" ::: "memory");
}
template <int N> __device__ __forceinline__ void cp_wait() {
    asm volatile("cp.async.wait_group %0;" :: "n"(N) : "memory");
}
__device__ __forceinline__ void ldsm4(uint32_t& r0, uint32_t& r1,
                                      uint32_t& r2, uint32_t& r3, uint32_t a) {
    asm volatile("ldmatrix.sync.aligned.m8n8.x4.shared.b16 {%0,%1,%2,%3}, [%4];"
                 : "=r"(r0), "=r"(r1), "=r"(r2), "=r"(r3) : "r"(a));
}
__device__ __forceinline__ void mma16816(float* c, const uint32_t* a,
                                         const uint32_t* b) {
    asm volatile(
        "mma.sync.aligned.m16n8k16.row.col.f32.bf16.bf16.f32 "
        "{%0,%1,%2,%3}, {%4,%5,%6,%7}, {%8,%9}, {%0,%1,%2,%3};"
        : "+f"(c[0]), "+f"(c[1]), "+f"(c[2]), "+f"(c[3])
        : "r"(a[0]), "r"(a[1]), "r"(a[2]), "r"(a[3]), "r"(b[0]), "r"(b[1]));
}
#define SW128(x) ((x) ^ (((x) >> 3) & 0x70))

// order-preserving float<->uint for atomicMax
__device__ __forceinline__ unsigned fenc(float f) {
    unsigned u = __float_as_uint(f);
    return (u & 0x80000000u) ? ~u : (u | 0x80000000u);
}
__device__ __forceinline__ float fdec(unsigned u) {
    return (u & 0x80000000u) ? __uint_as_float(u ^ 0x80000000u)
                             : __uint_as_float(~u);
}

// -------------------- setup kernels -----------------------------------------
__global__ void k_zero() {
    int64_t tid = (int64_t)blockIdx.x * blockDim.x + threadIdx.x;
    int64_t stride = (int64_t)gridDim.x * blockDim.x;
    for (int64_t i = tid; i < (int64_t)K * D; i += stride) g_wsum[i] = 0.0f;
    for (int64_t i = tid; i < K; i += stride) g_cnt[i] = 0.0f;
    for (int64_t i = tid; i < B; i += stride) g_ccnt[i] = 0;
    if (tid == 0) g_loss = 0.0f;
}

__global__ void k_cast_z(const float* __restrict__ z) {
    int64_t i = (int64_t)blockIdx.x * blockDim.x + threadIdx.x;
    int64_t n4 = (int64_t)B * D / 4;
    int64_t stride = (int64_t)gridDim.x * blockDim.x;
    for (; i < n4; i += stride) {
        float4 v = ((const float4*)z)[i];
        __nv_bfloat162* p = (__nv_bfloat162*)g_a0 + i * 2;
        __nv_bfloat162 t;
        t.x = __float2bfloat16_rn(v.x); t.y = __float2bfloat16_rn(v.y); p[0] = t;
        t.x = __float2bfloat16_rn(v.z); t.y = __float2bfloat16_rn(v.w); p[1] = t;
    }
}

// normalize codebook rows -> fp32 g_cbn + bf16 g_b0. one block per row.
__global__ void k_norm_cb(const float* __restrict__ cb) {
    __shared__ float red[256];
    int k = blockIdx.x;
    int t = threadIdx.x;
    float4 v = ((const float4*)(cb + (size_t)k * D))[t];
    red[t] = v.x * v.x + v.y * v.y + v.z * v.z + v.w * v.w;
    __syncthreads();
    for (int s = 128; s > 0; s >>= 1) {
        if (t < s) red[t] += red[t + s];
        __syncthreads();
    }
    float denom = fmaxf(sqrtf(red[0]), NORM_EPS);
    float4 o;
    o.x = v.x / denom; o.y = v.y / denom; o.z = v.z / denom; o.w = v.w / denom;
    ((float4*)(g_cbn + (size_t)k * D))[t] = o;
    __nv_bfloat162* p = (__nv_bfloat162*)g_b0 + (size_t)k * (D / 2) + t * 2;
    __nv_bfloat162 x;
    x.x = __float2bfloat16_rn(o.x); x.y = __float2bfloat16_rn(o.y); p[0] = x;
    x.x = __float2bfloat16_rn(o.z); x.y = __float2bfloat16_rn(o.w); p[1] = x;
}

// -------------------- approx bf16 GEMM + candidate harvest ------------------
// CTA tile 128(M) x 256(N); 8 warps = 2(M) x 4(N); warp tile 64x64.
// 8 ldsm.x4 -> 32 MMAs per k16 step (4 MMA/LDSM, 1.5x less smem-port traffic
// per FLOP than the 32x64 tile). acc[4][8][4] = 128 regs, occ 1.
#define DKC   64
#define NDK   (D / DKC)               // 16
#define NT    (K / 256)               // 32
#define A_BYTES 16384                 // 128 rows x 128B
#define B_BYTES 32768                 // 256 rows x 128B
#define STAGE_B (A_BYTES + B_BYTES)   // 48 KB
#define DYN_SMEM (2 * STAGE_B)        // 96 KB

__global__ __launch_bounds__(256, 1)
void k_approx(int dummy) {
    extern __shared__ char dyn[];
    __shared__ unsigned srowmax[128];
    uint32_t sbase = smem_u32(dyn);

    int tid = threadIdx.x;
    int lane = tid & 31;
    int wid = tid >> 5;
    int warp_m = wid >> 2;            // 0..1
    int warp_n = wid & 3;             // 0..3
    int g = lane >> 2;                // 0..7
    int tig = lane & 3;               // 0..3
    int row0 = blockIdx.x * 128;

    int lm_r = lane & 15;
    int lm_c = (lane >> 4) << 4;

    if (tid < 128) srowmax[tid] = 0u;   // < fenc of any float
    __syncthreads();

    const __nv_bfloat16* asrc0 = g_a0 + (size_t)row0 * D;

    for (int nt = 0; nt < NT; nt++) {
        const __nv_bfloat16* bsrc0 = g_b0 + (size_t)(nt * 256) * D;

        float acc[4][8][4];
#pragma unroll
        for (int i = 0; i < 4; i++)
#pragma unroll
            for (int j = 0; j < 8; j++)
#pragma unroll
                for (int q = 0; q < 4; q++) acc[i][j][q] = 0.0f;

        // prologue: stage 0 <- dk 0
        {
            uint32_t sb = sbase;
#pragma unroll
            for (int it = 0; it < 4; it++) {          // A: 1024 16B-lines
                int c = tid + 256 * it;
                int r = c >> 3, ch = c & 7;
                cp_async16(sb + SW128(r * 128 + ch * 16),
                           asrc0 + (size_t)r * D + ch * 8);
            }
#pragma unroll
            for (int it = 0; it < 8; it++) {          // B: 2048 16B-lines
                int c = tid + 256 * it;
                int r = c >> 3, ch = c & 7;
                cp_async16(sb + A_BYTES + SW128(r * 128 + ch * 16),
                           bsrc0 + (size_t)r * D + ch * 8);
            }
            cp_commit();
        }

        for (int dk = 0; dk < NDK; dk++) {
            int s = dk & 1;
            if (dk + 1 < NDK) {
                uint32_t sb = sbase + (s ^ 1) * STAGE_B;
                int koff = (dk + 1) * DKC;
#pragma unroll
                for (int it = 0; it < 4; it++) {
                    int c = tid + 256 * it;
                    int r = c >> 3, ch = c & 7;
                    cp_async16(sb + SW128(r * 128 + ch * 16),
                               asrc0 + koff + (size_t)r * D + ch * 8);
                }
#pragma unroll
                for (int it = 0; it < 8; it++) {
                    int c = tid + 256 * it;
                    int r = c >> 3, ch = c & 7;
                    cp_async16(sb + A_BYTES + SW128(r * 128 + ch * 16),
                               bsrc0 + koff + (size_t)r * D + ch * 8);
                }
                cp_commit();
                cp_wait<1>();
            } else {
                cp_wait<0>();
            }
            __syncthreads();

            uint32_t stg = sbase + s * STAGE_B;
#pragma unroll
            for (int step = 0; step < 4; step++) {
                int kc = step * 32 + lm_c;
                uint32_t afr[4][4];
#pragma unroll
                for (int mi = 0; mi < 4; mi++) {
                    int r = warp_m * 64 + mi * 16 + lm_r;
                    ldsm4(afr[mi][0], afr[mi][1], afr[mi][2], afr[mi][3],
                          stg + SW128(r * 128 + kc));
                }
                uint32_t bfr[4][4];
#pragma unroll
                for (int nb = 0; nb < 4; nb++) {
                    int r = warp_n * 64 + nb * 16 + lm_r;
                    ldsm4(bfr[nb][0], bfr[nb][1], bfr[nb][2], bfr[nb][3],
                          stg + A_BYTES + SW128(r * 128 + kc));
                }
#pragma unroll
                for (int mi = 0; mi < 4; mi++) {
#pragma unroll
                    for (int nb = 0; nb < 4; nb++) {
                        uint32_t b0[2] = { bfr[nb][0], bfr[nb][2] };
                        uint32_t b1[2] = { bfr[nb][1], bfr[nb][3] };
                        mma16816(acc[mi][nb * 2 + 0], afr[mi], b0);
                        mma16816(acc[mi][nb * 2 + 1], afr[mi], b1);
                    }
                }
            }
            __syncthreads();   // all warps done with stage s before overwrite
        }

        // ---- epilogue: running max + candidate insert
#pragma unroll
        for (int mi = 0; mi < 4; mi++) {
#pragma unroll
            for (int kk = 0; kk < 2; kk++) {
                int lrow = warp_m * 64 + mi * 16 + kk * 8 + g;
                float m = -INFINITY;
#pragma unroll
                for (int j = 0; j < 8; j++) {
                    m = fmaxf(m, acc[mi][j][kk * 2 + 0]);
                    m = fmaxf(m, acc[mi][j][kk * 2 + 1]);
                }
                atomicMax(&srowmax[lrow], fenc(m));
            }
        }
        __syncthreads();
#pragma unroll
        for (int mi = 0; mi < 4; mi++) {
#pragma unroll
            for (int kk = 0; kk < 2; kk++) {
                int lrow = warp_m * 64 + mi * 16 + kk * 8 + g;
                float thr = fdec(srowmax[lrow]) - MARGIN;
                float m = -INFINITY;
#pragma unroll
                for (int j = 0; j < 8; j++) {
                    m = fmaxf(m, acc[mi][j][kk * 2 + 0]);
                    m = fmaxf(m, acc[mi][j][kk * 2 + 1]);
                }
                if (m < thr) continue;
#pragma unroll
                for (int j = 0; j < 8; j++) {
#pragma unroll
                    for (int h = 0; h < 2; h++) {
                        float v = acc[mi][j][kk * 2 + h];
                        if (v >= thr) {
                            int col = nt * 256 + warp_n * 64 + j * 8 + tig * 2 + h;
                            int grow = row0 + lrow;
                            int p = atomicAdd(&g_ccnt[grow], 1);
                            if (p < CAP) g_cand[(size_t)grow * CAP + p] = col;
                        }
                    }
                }
            }
        }
        // next iteration's top-of-loop __syncthreads orders srowmax reuse
    }
}

// -------------------- fused exact rescore + scatter (one block per row) -----
__global__ __launch_bounds__(256)
void k_finish(const float* __restrict__ z,
              const float* __restrict__ cb,
              float* __restrict__ out) {
    __shared__ float4 zs[256];         // the z row
    __shared__ float red[256];
    __shared__ float wval[8];
    __shared__ int   widx[8];
    __shared__ int   s_id;

    int b = blockIdx.x;
    int t = threadIdx.x;
    int lane = t & 31;
    int w = t >> 5;

    float4 zv = ((const float4*)(z + (size_t)b * D))[t];
    zs[t] = zv;
    __syncthreads();

    int cnt = g_ccnt[b];
    if (cnt > CAP) cnt = CAP;

    float bv = -INFINITY;
    int   bi = 0x7fffffff;
    for (int c = w; c < cnt; c += 8) {
        int idx = g_cand[(size_t)b * CAP + c];
        const float4* cp = (const float4*)(g_cbn + (size_t)idx * D);
        float s = 0.0f;
#pragma unroll
        for (int i = 0; i < 8; i++) {
            float4 zr = zs[i * 32 + lane];
            float4 cv = cp[i * 32 + lane];
            s += zr.x * cv.x + zr.y * cv.y + zr.z * cv.z + zr.w * cv.w;
        }
#pragma unroll
        for (int o = 16; o > 0; o >>= 1) s += __shfl_xor_sync(0xFFFFFFFFu, s, o);
        if (s > bv || (s == bv && idx < bi)) { bv = s; bi = idx; }
    }
    if (lane == 0) { wval[w] = bv; widx[w] = bi; }
    __syncthreads();
    if (t == 0) {
        float fv = wval[0]; int fi = widx[0];
#pragma unroll
        for (int i = 1; i < 8; i++) {
            if (wval[i] > fv || (wval[i] == fv && widx[i] < fi)) {
                fv = wval[i]; fi = widx[i];
            }
        }
        s_id = fi;
        out[OFF_IDS + b] = (float)fi;
    }
    __syncthreads();
    int id = s_id;

    float4 qv = ((const float4*)(cb + (size_t)id * D))[t];
    float4 zq;
    zq.x = zv.x + (qv.x - zv.x);
    zq.y = zv.y + (qv.y - zv.y);
    zq.z = zv.z + (qv.z - zv.z);
    zq.w = zv.w + (qv.w - zv.w);
    ((float4*)(out + OFF_ZQ + (size_t)b * D))[t] = zq;

    float dx = zv.x - qv.x, dy = zv.y - qv.y, dz = zv.z - qv.z, dw = zv.w - qv.w;
    red[t] = dx * dx + dy * dy + dz * dz + dw * dw;

    float* wrow = g_wsum + (size_t)id * D + t * 4;
    atomicAdd(wrow + 0, zv.x);
    atomicAdd(wrow + 1, zv.y);
    atomicAdd(wrow + 2, zv.z);
    atomicAdd(wrow + 3, zv.w);

    __syncthreads();
    for (int s = 128; s > 0; s >>= 1) {
        if (t < s) red[t] += red[t + s];
        __syncthreads();
    }
    if (t == 0) {
        atomicAdd(&g_loss, red[0]);
        atomicAdd(&g_cnt[id], 1.0f);
    }
}

// -------------------- epilogue kernels --------------------------------------
__global__ void k_count(const float* __restrict__ ema_count,
                        float* __restrict__ out) {
    int k = blockIdx.x * blockDim.x + threadIdx.x;
    if (k < K) {
        float nc = DECAY * ema_count[k] + ONE_M_D * g_cnt[k];
        g_ncnt[k] = nc;
        out[OFF_CNT + k] = nc;
    }
}

__global__ void k_final(const float* __restrict__ ema_weight,
                        float* __restrict__ out) {
    int64_t i4 = (int64_t)blockIdx.x * blockDim.x + threadIdx.x;
    if (i4 >= (int64_t)K * D / 4) return;
    int row = (int)(i4 >> 8);
    float4 ew = ((const float4*)ema_weight)[i4];
    float4 ws = ((const float4*)g_wsum)[i4];
    float w0 = DECAY * ew.x + ONE_M_D * ws.x;
    float w1 = DECAY * ew.y + ONE_M_D * ws.y;
    float w2 = DECAY * ew.z + ONE_M_D * ws.z;
    float w3 = DECAY * ew.w + ONE_M_D * ws.w;
    int64_t base = i4 * 4;
    out[OFF_W + base + 0] = w0;
    out[OFF_W + base + 1] = w1;
    out[OFF_W + base + 2] = w2;
    out[OFF_W + base + 3] = w3;
    float denom = g_ncnt[row] + EPS;
    out[OFF_CB + base + 0] = w0 / denom;
    out[OFF_CB + base + 1] = w1 / denom;
    out[OFF_CB + base + 2] = w2 / denom;
    out[OFF_CB + base + 3] = w3 / denom;
}

__global__ void k_loss(float* __restrict__ out) {
    out[OFF_LOSS] = COMMIT * (g_loss / (float)((int64_t)B * D));
}

// ---------------------------------------------------------------------------
extern "C" void kernel_launch(void* const* d_in, const int* in_sizes, int n_in,
                              void* d_out, int out_size) {
    const float* z          = (const float*)d_in[0];
    const float* codebook   = (const float*)d_in[1];
    const float* ema_count  = (const float*)d_in[2];
    const float* ema_weight = (const float*)d_in[3];
    float* out = (float*)d_out;

    cudaFuncSetAttribute(k_approx, cudaFuncAttributeMaxDynamicSharedMemorySize,
                         DYN_SMEM);

    k_zero<<<2048, 256>>>();
    k_cast_z<<<4096, 256>>>(z);
    k_norm_cb<<<K, 256>>>(codebook);
    k_approx<<<B / 128, 256, DYN_SMEM>>>(0);
    k_finish<<<B, 256>>>(z, codebook, out);
    k_count<<<(K + 255) / 256, 256>>>(ema_count, out);
    k_final<<<(K * D / 4 + 255) / 256, 256>>>(ema_weight, out);
    k_loss<<<1, 1>>>(out);
}

// round 13
// speedup vs baseline: 1.0528x; 1.0528x over previous
#include <cuda_runtime.h>
#include <cuda_bf16.h>
#include <math.h>
#include <stdint.h>

// Problem constants
#define B  32768
#define K  8192
#define D  1024
#define DECAY   0.99f
#define ONE_M_D 0.01f
#define EPS     1e-5f
#define COMMIT  0.25f
#define NORM_EPS 1e-12f

// Candidate machinery
#define CAP    64
#define MARGIN 0.15f

// Output layout (flattened tuple, float32)
#define OFF_ZQ   0
#define OFF_IDS  (B*D)
#define OFF_LOSS (OFF_IDS + B)
#define OFF_CB   (OFF_LOSS + 1)              // odd -> no float4 stores
#define OFF_CNT  (OFF_CB + K*D)
#define OFF_W    (OFF_CNT + K)               // odd -> no float4 stores

// -------------------- device scratch (no allocation allowed) ----------------
__device__ __align__(16) __nv_bfloat16 g_a0[(size_t)B * D];   // bf16(z)
__device__ __align__(16) __nv_bfloat16 g_b0[(size_t)K * D];   // bf16(cb_norm)
__device__ __align__(16) float g_cbn[(size_t)K * D];          // fp32 cb_norm
__device__ __align__(16) float g_wsum[K * D];
__device__ int   g_cand[(size_t)B * CAP];
__device__ int   g_ccnt[B];
__device__ float g_cnt[K];
__device__ float g_ncnt[K];
__device__ float g_loss;

// -------------------- PTX helpers (compute_103-safe) ------------------------
__device__ __forceinline__ uint32_t smem_u32(const void* p) {
    uint32_t a;
    asm("{ .reg .u64 t; cvta.to.shared.u64 t, %1; cvt.u32.u64 %0, t; }"
        : "=r"(a) : "l"(p));
    return a;
}
__device__ __forceinline__ void cp_async16(uint32_t dst, const void* src) {
    asm volatile("cp.async.cg.shared.global [%0], [%1], 16;"
                 :: "r"(dst), "l"(src) : "memory");
}
__device__ __forceinline__ void cp_commit() {
    asm volatile("cp.async.commit_group;" ::: "memory");
}
template <int N> __device__ __forceinline__ void cp_wait() {
    asm volatile("cp.async.wait_group %0;" :: "n"(N) : "memory");
}
__device__ __forceinline__ void ldsm4(uint32_t& r0, uint32_t& r1,
                                      uint32_t& r2, uint32_t& r3, uint32_t a) {
    asm volatile("ldmatrix.sync.aligned.m8n8.x4.shared.b16 {%0,%1,%2,%3}, [%4];"
                 : "=r"(r0), "=r"(r1), "=r"(r2), "=r"(r3) : "r"(a));
}
__device__ __forceinline__ void mma16816(float* c, const uint32_t* a,
                                         const uint32_t* b) {
    asm volatile(
        "mma.sync.aligned.m16n8k16.row.col.f32.bf16.bf16.f32 "
        "{%0,%1,%2,%3}, {%4,%5,%6,%7}, {%8,%9}, {%0,%1,%2,%3};"
        : "+f"(c[0]), "+f"(c[1]), "+f"(c[2]), "+f"(c[3])
        : "r"(a[0]), "r"(a[1]), "r"(a[2]), "r"(a[3]), "r"(b[0]), "r"(b[1]));
}
#define SW128(x) ((x) ^ (((x) >> 3) & 0x70))

// order-preserving float<->uint for atomicMax
__device__ __forceinline__ unsigned fenc(float f) {
    unsigned u = __float_as_uint(f);
    return (u & 0x80000000u) ? ~u : (u | 0x80000000u);
}
__device__ __forceinline__ float fdec(unsigned u) {
    return (u & 0x80000000u) ? __uint_as_float(u ^ 0x80000000u)
                             : __uint_as_float(~u);
}

// -------------------- setup kernels -----------------------------------------
__global__ void k_zero() {
    int64_t tid = (int64_t)blockIdx.x * blockDim.x + threadIdx.x;
    int64_t stride = (int64_t)gridDim.x * blockDim.x;
    for (int64_t i = tid; i < (int64_t)K * D; i += stride) g_wsum[i] = 0.0f;
    for (int64_t i = tid; i < K; i += stride) g_cnt[i] = 0.0f;
    for (int64_t i = tid; i < B; i += stride) g_ccnt[i] = 0;
    if (tid == 0) g_loss = 0.0f;
}

__global__ void k_cast_z(const float* __restrict__ z) {
    int64_t i = (int64_t)blockIdx.x * blockDim.x + threadIdx.x;
    int64_t n4 = (int64_t)B * D / 4;
    int64_t stride = (int64_t)gridDim.x * blockDim.x;
    for (; i < n4; i += stride) {
        float4 v = ((const float4*)z)[i];
        __nv_bfloat162* p = (__nv_bfloat162*)g_a0 + i * 2;
        __nv_bfloat162 t;
        t.x = __float2bfloat16_rn(v.x); t.y = __float2bfloat16_rn(v.y); p[0] = t;
        t.x = __float2bfloat16_rn(v.z); t.y = __float2bfloat16_rn(v.w); p[1] = t;
    }
}

// normalize codebook rows -> fp32 g_cbn + bf16 g_b0. one block per row.
__global__ void k_norm_cb(const float* __restrict__ cb) {
    __shared__ float red[256];
    int k = blockIdx.x;
    int t = threadIdx.x;
    float4 v = ((const float4*)(cb + (size_t)k * D))[t];
    red[t] = v.x * v.x + v.y * v.y + v.z * v.z + v.w * v.w;
    __syncthreads();
    for (int s = 128; s > 0; s >>= 1) {
        if (t < s) red[t] += red[t + s];
        __syncthreads();
    }
    float denom = fmaxf(sqrtf(red[0]), NORM_EPS);
    float4 o;
    o.x = v.x / denom; o.y = v.y / denom; o.z = v.z / denom; o.w = v.w / denom;
    ((float4*)(g_cbn + (size_t)k * D))[t] = o;
    __nv_bfloat162* p = (__nv_bfloat162*)g_b0 + (size_t)k * (D / 2) + t * 2;
    __nv_bfloat162 x;
    x.x = __float2bfloat16_rn(o.x); x.y = __float2bfloat16_rn(o.y); p[0] = x;
    x.x = __float2bfloat16_rn(o.z); x.y = __float2bfloat16_rn(o.w); p[1] = x;
}

// -------------------- approx bf16 GEMM + candidate harvest ------------------
// CTA tile 64(M) x 128(N); 4 warps = 2(M) x 2(N); warp tile 32x64 (same as
// the proven R8 shape). Small CTA -> 4 CTAs/SM (occ 2x R8) to keep the HMMA
// pipe fed through ldsm/barrier gaps. 2-stage cp.async pipeline.
#define DKC   64
#define NDK   (D / DKC)               // 16
#define NT    (K / 128)               // 64
#define A_BYTES 8192                  // 64 rows x 128B
#define B_BYTES 16384                 // 128 rows x 128B
#define STAGE_B (A_BYTES + B_BYTES)   // 24 KB
#define DYN_SMEM (2 * STAGE_B)        // 48 KB

__global__ __launch_bounds__(128, 4)
void k_approx(int dummy) {
    extern __shared__ char dyn[];
    __shared__ unsigned srowmax[64];
    uint32_t sbase = smem_u32(dyn);

    int tid = threadIdx.x;
    int lane = tid & 31;
    int wid = tid >> 5;
    int warp_m = wid >> 1;            // 0..1
    int warp_n = wid & 1;             // 0..1
    int g = lane >> 2;                // 0..7
    int tig = lane & 3;               // 0..3
    int row0 = blockIdx.x * 64;

    int lm_r = lane & 15;
    int lm_c = (lane >> 4) << 4;

    if (tid < 64) srowmax[tid] = 0u;   // < fenc of any float
    __syncthreads();

    const __nv_bfloat16* asrc0 = g_a0 + (size_t)row0 * D;

    for (int nt = 0; nt < NT; nt++) {
        const __nv_bfloat16* bsrc0 = g_b0 + (size_t)(nt * 128) * D;

        float acc[2][8][4];
#pragma unroll
        for (int i = 0; i < 2; i++)
#pragma unroll
            for (int j = 0; j < 8; j++)
#pragma unroll
                for (int q = 0; q < 4; q++) acc[i][j][q] = 0.0f;

        // prologue: stage 0 <- dk 0 (A 512 lines + B 1024 lines, 128 thr)
        {
            uint32_t sb = sbase;
#pragma unroll
            for (int it = 0; it < 4; it++) {
                int c = tid + 128 * it;
                int r = c >> 3, ch = c & 7;
                cp_async16(sb + SW128(r * 128 + ch * 16),
                           asrc0 + (size_t)r * D + ch * 8);
            }
#pragma unroll
            for (int it = 0; it < 8; it++) {
                int c = tid + 128 * it;
                int r = c >> 3, ch = c & 7;
                cp_async16(sb + A_BYTES + SW128(r * 128 + ch * 16),
                           bsrc0 + (size_t)r * D + ch * 8);
            }
            cp_commit();
        }

        for (int dk = 0; dk < NDK; dk++) {
            int s = dk & 1;
            if (dk + 1 < NDK) {
                uint32_t sb = sbase + (s ^ 1) * STAGE_B;
                int koff = (dk + 1) * DKC;
#pragma unroll
                for (int it = 0; it < 4; it++) {
                    int c = tid + 128 * it;
                    int r = c >> 3, ch = c & 7;
                    cp_async16(sb + SW128(r * 128 + ch * 16),
                               asrc0 + koff + (size_t)r * D + ch * 8);
                }
#pragma unroll
                for (int it = 0; it < 8; it++) {
                    int c = tid + 128 * it;
                    int r = c >> 3, ch = c & 7;
                    cp_async16(sb + A_BYTES + SW128(r * 128 + ch * 16),
                               bsrc0 + koff + (size_t)r * D + ch * 8);
                }
                cp_commit();
                cp_wait<1>();
            } else {
                cp_wait<0>();
            }
            __syncthreads();

            uint32_t stg = sbase + s * STAGE_B;
#pragma unroll
            for (int step = 0; step < 4; step++) {
                int kc = step * 32 + lm_c;
                uint32_t afr[2][4];
#pragma unroll
                for (int mi = 0; mi < 2; mi++) {
                    int r = warp_m * 32 + mi * 16 + lm_r;
                    ldsm4(afr[mi][0], afr[mi][1], afr[mi][2], afr[mi][3],
                          stg + SW128(r * 128 + kc));
                }
                uint32_t bfr[4][4];
#pragma unroll
                for (int nb = 0; nb < 4; nb++) {
                    int r = warp_n * 64 + nb * 16 + lm_r;
                    ldsm4(bfr[nb][0], bfr[nb][1], bfr[nb][2], bfr[nb][3],
                          stg + A_BYTES + SW128(r * 128 + kc));
                }
#pragma unroll
                for (int mi = 0; mi < 2; mi++) {
#pragma unroll
                    for (int nb = 0; nb < 4; nb++) {
                        uint32_t b0[2] = { bfr[nb][0], bfr[nb][2] };
                        uint32_t b1[2] = { bfr[nb][1], bfr[nb][3] };
                        mma16816(acc[mi][nb * 2 + 0], afr[mi], b0);
                        mma16816(acc[mi][nb * 2 + 1], afr[mi], b1);
                    }
                }
            }
            __syncthreads();   // all warps done with stage s before overwrite
        }

        // ---- epilogue: running max + candidate insert
#pragma unroll
        for (int i = 0; i < 2; i++) {
#pragma unroll
            for (int kk = 0; kk < 2; kk++) {
                int lrow = warp_m * 32 + i * 16 + kk * 8 + g;
                float m = -INFINITY;
#pragma unroll
                for (int j = 0; j < 8; j++) {
                    m = fmaxf(m, acc[i][j][kk * 2 + 0]);
                    m = fmaxf(m, acc[i][j][kk * 2 + 1]);
                }
                atomicMax(&srowmax[lrow], fenc(m));
            }
        }
        __syncthreads();
#pragma unroll
        for (int i = 0; i < 2; i++) {
#pragma unroll
            for (int kk = 0; kk < 2; kk++) {
                int lrow = warp_m * 32 + i * 16 + kk * 8 + g;
                float thr = fdec(srowmax[lrow]) - MARGIN;
                float m = -INFINITY;
#pragma unroll
                for (int j = 0; j < 8; j++) {
                    m = fmaxf(m, acc[i][j][kk * 2 + 0]);
                    m = fmaxf(m, acc[i][j][kk * 2 + 1]);
                }
                if (m < thr) continue;
#pragma unroll
                for (int j = 0; j < 8; j++) {
#pragma unroll
                    for (int h = 0; h < 2; h++) {
                        float v = acc[i][j][kk * 2 + h];
                        if (v >= thr) {
                            int col = nt * 128 + warp_n * 64 + j * 8 + tig * 2 + h;
                            int grow = row0 + lrow;
                            int p = atomicAdd(&g_ccnt[grow], 1);
                            if (p < CAP) g_cand[(size_t)grow * CAP + p] = col;
                        }
                    }
                }
            }
        }
        // next iteration's top-of-loop __syncthreads orders srowmax reuse
    }
}

// -------------------- fused exact rescore + scatter (one block per row) -----
__global__ __launch_bounds__(256)
void k_finish(const float* __restrict__ z,
              const float* __restrict__ cb,
              float* __restrict__ out) {
    __shared__ float4 zs[256];         // the z row
    __shared__ float red[256];
    __shared__ float wval[8];
    __shared__ int   widx[8];
    __shared__ int   s_id;

    int b = blockIdx.x;
    int t = threadIdx.x;
    int lane = t & 31;
    int w = t >> 5;

    float4 zv = ((const float4*)(z + (size_t)b * D))[t];
    zs[t] = zv;
    __syncthreads();

    int cnt = g_ccnt[b];
    if (cnt > CAP) cnt = CAP;

    float bv = -INFINITY;
    int   bi = 0x7fffffff;
    for (int c = w; c < cnt; c += 8) {
        int idx = g_cand[(size_t)b * CAP + c];
        const float4* cp = (const float4*)(g_cbn + (size_t)idx * D);
        float s = 0.0f;
#pragma unroll
        for (int i = 0; i < 8; i++) {
            float4 zr = zs[i * 32 + lane];
            float4 cv = cp[i * 32 + lane];
            s += zr.x * cv.x + zr.y * cv.y + zr.z * cv.z + zr.w * cv.w;
        }
#pragma unroll
        for (int o = 16; o > 0; o >>= 1) s += __shfl_xor_sync(0xFFFFFFFFu, s, o);
        if (s > bv || (s == bv && idx < bi)) { bv = s; bi = idx; }
    }
    if (lane == 0) { wval[w] = bv; widx[w] = bi; }
    __syncthreads();
    if (t == 0) {
        float fv = wval[0]; int fi = widx[0];
#pragma unroll
        for (int i = 1; i < 8; i++) {
            if (wval[i] > fv || (wval[i] == fv && widx[i] < fi)) {
                fv = wval[i]; fi = widx[i];
            }
        }
        s_id = fi;
        out[OFF_IDS + b] = (float)fi;
    }
    __syncthreads();
    int id = s_id;

    float4 qv = ((const float4*)(cb + (size_t)id * D))[t];
    float4 zq;
    zq.x = zv.x + (qv.x - zv.x);
    zq.y = zv.y + (qv.y - zv.y);
    zq.z = zv.z + (qv.z - zv.z);
    zq.w = zv.w + (qv.w - zv.w);
    ((float4*)(out + OFF_ZQ + (size_t)b * D))[t] = zq;

    float dx = zv.x - qv.x, dy = zv.y - qv.y, dz = zv.z - qv.z, dw = zv.w - qv.w;
    red[t] = dx * dx + dy * dy + dz * dz + dw * dw;

    float* wrow = g_wsum + (size_t)id * D + t * 4;
    atomicAdd(wrow + 0, zv.x);
    atomicAdd(wrow + 1, zv.y);
    atomicAdd(wrow + 2, zv.z);
    atomicAdd(wrow + 3, zv.w);

    __syncthreads();
    for (int s = 128; s > 0; s >>= 1) {
        if (t < s) red[t] += red[t + s];
        __syncthreads();
    }
    if (t == 0) {
        atomicAdd(&g_loss, red[0]);
        atomicAdd(&g_cnt[id], 1.0f);
    }
}

// -------------------- epilogue kernels --------------------------------------
__global__ void k_count(const float* __restrict__ ema_count,
                        float* __restrict__ out) {
    int k = blockIdx.x * blockDim.x + threadIdx.x;
    if (k < K) {
        float nc = DECAY * ema_count[k] + ONE_M_D * g_cnt[k];
        g_ncnt[k] = nc;
        out[OFF_CNT + k] = nc;
    }
}

__global__ void k_final(const float* __restrict__ ema_weight,
                        float* __restrict__ out) {
    int64_t i4 = (int64_t)blockIdx.x * blockDim.x + threadIdx.x;
    if (i4 >= (int64_t)K * D / 4) return;
    int row = (int)(i4 >> 8);
    float4 ew = ((const float4*)ema_weight)[i4];
    float4 ws = ((const float4*)g_wsum)[i4];
    float w0 = DECAY * ew.x + ONE_M_D * ws.x;
    float w1 = DECAY * ew.y + ONE_M_D * ws.y;
    float w2 = DECAY * ew.z + ONE_M_D * ws.z;
    float w3 = DECAY * ew.w + ONE_M_D * ws.w;
    int64_t base = i4 * 4;
    out[OFF_W + base + 0] = w0;
    out[OFF_W + base + 1] = w1;
    out[OFF_W + base + 2] = w2;
    out[OFF_W + base + 3] = w3;
    float denom = g_ncnt[row] + EPS;
    out[OFF_CB + base + 0] = w0 / denom;
    out[OFF_CB + base + 1] = w1 / denom;
    out[OFF_CB + base + 2] = w2 / denom;
    out[OFF_CB + base + 3] = w3 / denom;
}

__global__ void k_loss(float* __restrict__ out) {
    out[OFF_LOSS] = COMMIT * (g_loss / (float)((int64_t)B * D));
}

// ---------------------------------------------------------------------------
extern "C" void kernel_launch(void* const* d_in, const int* in_sizes, int n_in,
                              void* d_out, int out_size) {
    const float* z          = (const float*)d_in[0];
    const float* codebook   = (const float*)d_in[1];
    const float* ema_count  = (const float*)d_in[2];
    const float* ema_weight = (const float*)d_in[3];
    float* out = (float*)d_out;

    cudaFuncSetAttribute(k_approx, cudaFuncAttributeMaxDynamicSharedMemorySize,
                         DYN_SMEM);

    k_zero<<<2048, 256>>>();
    k_cast_z<<<4096, 256>>>(z);
    k_norm_cb<<<K, 256>>>(codebook);
    k_approx<<<B / 64, 128, DYN_SMEM>>>(0);
    k_finish<<<B, 256>>>(z, codebook, out);
    k_count<<<(K + 255) / 256, 256>>>(ema_count, out);
    k_final<<<(K * D / 4 + 255) / 256, 256>>>(ema_weight, out);
    k_loss<<<1, 1>>>(out);
}

// round 14
// speedup vs baseline: 1.1453x; 1.0879x over previous
#include <cuda_runtime.h>
#include <cuda_bf16.h>
#include <math.h>
#include <stdint.h>

// Problem constants
#define B  32768
#define K  8192
#define D  1024
#define DECAY   0.99f
#define ONE_M_D 0.01f
#define EPS     1e-5f
#define COMMIT  0.25f
#define NORM_EPS 1e-12f

// Candidate machinery
#define CAP    64
#define MARGIN 0.15f

// Output layout (flattened tuple, float32)
#define OFF_ZQ   0
#define OFF_IDS  (B*D)
#define OFF_LOSS (OFF_IDS + B)
#define OFF_CB   (OFF_LOSS + 1)              // odd -> no float4 stores
#define OFF_CNT  (OFF_CB + K*D)
#define OFF_W    (OFF_CNT + K)               // odd -> no float4 stores

// -------------------- device scratch (no allocation allowed) ----------------
__device__ __align__(16) __nv_bfloat16 g_a0[(size_t)B * D];   // bf16(z)
__device__ __align__(16) __nv_bfloat16 g_b0[(size_t)K * D];   // bf16(cb_norm)
__device__ __align__(16) float g_cbn[(size_t)K * D];          // fp32 cb_norm
__device__ __align__(16) float g_wsum[K * D];
__device__ int   g_cand[(size_t)B * CAP];
__device__ int   g_ccnt[B];
__device__ float g_cnt[K];
__device__ int   g_ids[B];
__device__ float g_loss;

// -------------------- PTX helpers (compute_103-safe) ------------------------
__device__ __forceinline__ uint32_t smem_u32(const void* p) {
    uint32_t a;
    asm("{ .reg .u64 t; cvta.to.shared.u64 t, %1; cvt.u32.u64 %0, t; }"
        : "=r"(a) : "l"(p));
    return a;
}
__device__ __forceinline__ void cp_async16(uint32_t dst, const void* src) {
    asm volatile("cp.async.cg.shared.global [%0], [%1], 16;"
                 :: "r"(dst), "l"(src) : "memory");
}
__device__ __forceinline__ void cp_commit() {
    asm volatile("cp.async.commit_group;" ::: "memory");
}
template <int N> __device__ __forceinline__ void cp_wait() {
    asm volatile("cp.async.wait_group %0;" :: "n"(N) : "memory");
}
__device__ __forceinline__ void ldsm4(uint32_t& r0, uint32_t& r1,
                                      uint32_t& r2, uint32_t& r3, uint32_t a) {
    asm volatile("ldmatrix.sync.aligned.m8n8.x4.shared.b16 {%0,%1,%2,%3}, [%4];"
                 : "=r"(r0), "=r"(r1), "=r"(r2), "=r"(r3) : "r"(a));
}
__device__ __forceinline__ void mma16816(float* c, const uint32_t* a,
                                         const uint32_t* b) {
    asm volatile(
        "mma.sync.aligned.m16n8k16.row.col.f32.bf16.bf16.f32 "
        "{%0,%1,%2,%3}, {%4,%5,%6,%7}, {%8,%9}, {%0,%1,%2,%3};"
        : "+f"(c[0]), "+f"(c[1]), "+f"(c[2]), "+f"(c[3])
        : "r"(a[0]), "r"(a[1]), "r"(a[2]), "r"(a[3]), "r"(b[0]), "r"(b[1]));
}
#define SW128(x) ((x) ^ (((x) >> 3) & 0x70))

// order-preserving float<->uint for atomicMax
__device__ __forceinline__ unsigned fenc(float f) {
    unsigned u = __float_as_uint(f);
    return (u & 0x80000000u) ? ~u : (u | 0x80000000u);
}
__device__ __forceinline__ float fdec(unsigned u) {
    return (u & 0x80000000u) ? __uint_as_float(u ^ 0x80000000u)
                             : __uint_as_float(~u);
}

// -------------------- setup: zero scratch + cast z to bf16 (one pass) -------
__global__ void k_prep(const float* __restrict__ z) {
    int64_t tid = (int64_t)blockIdx.x * blockDim.x + threadIdx.x;
    int64_t stride = (int64_t)gridDim.x * blockDim.x;
    // zero accumulators
    for (int64_t i = tid * 4; i < (int64_t)K * D; i += stride * 4)
        *(float4*)(g_wsum + i) = make_float4(0.f, 0.f, 0.f, 0.f);
    for (int64_t i = tid; i < K; i += stride) g_cnt[i] = 0.0f;
    for (int64_t i = tid; i < B; i += stride) g_ccnt[i] = 0;
    if (tid == 0) g_loss = 0.0f;
    // cast z -> bf16
    int64_t n4 = (int64_t)B * D / 4;
    for (int64_t i = tid; i < n4; i += stride) {
        float4 v = ((const float4*)z)[i];
        __nv_bfloat162* p = (__nv_bfloat162*)g_a0 + i * 2;
        __nv_bfloat162 t;
        t.x = __float2bfloat16_rn(v.x); t.y = __float2bfloat16_rn(v.y); p[0] = t;
        t.x = __float2bfloat16_rn(v.z); t.y = __float2bfloat16_rn(v.w); p[1] = t;
    }
}

// normalize codebook rows -> fp32 g_cbn + bf16 g_b0. one block per row.
__global__ void k_norm_cb(const float* __restrict__ cb) {
    __shared__ float red[256];
    int k = blockIdx.x;
    int t = threadIdx.x;
    float4 v = ((const float4*)(cb + (size_t)k * D))[t];
    red[t] = v.x * v.x + v.y * v.y + v.z * v.z + v.w * v.w;
    __syncthreads();
    for (int s = 128; s > 0; s >>= 1) {
        if (t < s) red[t] += red[t + s];
        __syncthreads();
    }
    float denom = fmaxf(sqrtf(red[0]), NORM_EPS);
    float4 o;
    o.x = v.x / denom; o.y = v.y / denom; o.z = v.z / denom; o.w = v.w / denom;
    ((float4*)(g_cbn + (size_t)k * D))[t] = o;
    __nv_bfloat162* p = (__nv_bfloat162*)g_b0 + (size_t)k * (D / 2) + t * 2;
    __nv_bfloat162 x;
    x.x = __float2bfloat16_rn(o.x); x.y = __float2bfloat16_rn(o.y); p[0] = x;
    x.x = __float2bfloat16_rn(o.z); x.y = __float2bfloat16_rn(o.w); p[1] = x;
}

// -------------------- approx bf16 GEMM + candidate harvest (R8 exact) -------
// CTA: 128 rows, sweeps 64 N-tiles of 128. 8 warps = 4(M) x 2(N), warp 32x64.
// Single bf16 product. Running per-row max in smem; values within MARGIN of
// the running max are appended to the row's global candidate list.
#define DKC   64
#define NDK   (D / DKC)               // 16
#define NT    (K / 128)               // 64
#define TILE_B 16384                  // 128 rows x 128 bytes (64 bf16 cols)
#define STAGE_B (2 * TILE_B)          // A tile + B tile = 32 KB
#define DYN_SMEM (2 * STAGE_B)        // 64 KB

__global__ __launch_bounds__(256, 2)
void k_approx(int dummy) {
    extern __shared__ char dyn[];
    __shared__ unsigned srowmax[128];
    uint32_t sbase = smem_u32(dyn);

    int tid = threadIdx.x;
    int lane = tid & 31;
    int wid = tid >> 5;
    int warp_m = wid >> 1;            // 0..3
    int warp_n = wid & 1;             // 0..1
    int g = lane >> 2;                // 0..7
    int tig = lane & 3;               // 0..3
    int row0 = blockIdx.x * 128;

    int lm_r = lane & 15;
    int lm_c = (lane >> 4) << 4;

    if (tid < 128) srowmax[tid] = 0u;   // < fenc of any float
    __syncthreads();

    const __nv_bfloat16* asrc0 = g_a0 + (size_t)row0 * D;

    for (int nt = 0; nt < NT; nt++) {
        const __nv_bfloat16* bsrc0 = g_b0 + (size_t)nt * 128 * D;

        float acc[2][8][4];
#pragma unroll
        for (int i = 0; i < 2; i++)
#pragma unroll
            for (int j = 0; j < 8; j++)
#pragma unroll
                for (int q = 0; q < 4; q++) acc[i][j][q] = 0.0f;

        // prologue: stage 0 <- dk 0 (A tile + B tile)
        {
            uint32_t sb = sbase;
#pragma unroll
            for (int t2 = 0; t2 < 2; t2++) {
                const __nv_bfloat16* src = t2 ? bsrc0 : asrc0;
#pragma unroll
                for (int it = 0; it < 4; it++) {
                    int c = tid + 256 * it;
                    int r = c >> 3, ch = c & 7;
                    cp_async16(sb + t2 * TILE_B + SW128(r * 128 + ch * 16),
                               src + (size_t)r * D + ch * 8);
                }
            }
            cp_commit();
        }

        for (int dk = 0; dk < NDK; dk++) {
            int s = dk & 1;
            if (dk + 1 < NDK) {
                uint32_t sb = sbase + (s ^ 1) * STAGE_B;
                int koff = (dk + 1) * DKC;
#pragma unroll
                for (int t2 = 0; t2 < 2; t2++) {
                    const __nv_bfloat16* src = (t2 ? bsrc0 : asrc0) + koff;
#pragma unroll
                    for (int it = 0; it < 4; it++) {
                        int c = tid + 256 * it;
                        int r = c >> 3, ch = c & 7;
                        cp_async16(sb + t2 * TILE_B + SW128(r * 128 + ch * 16),
                                   src + (size_t)r * D + ch * 8);
                    }
                }
                cp_commit();
                cp_wait<1>();
            } else {
                cp_wait<0>();
            }
            __syncthreads();

            uint32_t stg = sbase + s * STAGE_B;
#pragma unroll
            for (int step = 0; step < 4; step++) {
                int kc = step * 32 + lm_c;
                uint32_t afr[2][4];
#pragma unroll
                for (int mi = 0; mi < 2; mi++) {
                    int r = warp_m * 32 + mi * 16 + lm_r;
                    ldsm4(afr[mi][0], afr[mi][1], afr[mi][2], afr[mi][3],
                          stg + SW128(r * 128 + kc));
                }
                uint32_t bfr[4][4];
#pragma unroll
                for (int nb = 0; nb < 4; nb++) {
                    int r = warp_n * 64 + nb * 16 + lm_r;
                    ldsm4(bfr[nb][0], bfr[nb][1], bfr[nb][2], bfr[nb][3],
                          stg + TILE_B + SW128(r * 128 + kc));
                }
#pragma unroll
                for (int mi = 0; mi < 2; mi++) {
#pragma unroll
                    for (int nb = 0; nb < 4; nb++) {
                        uint32_t b0[2] = { bfr[nb][0], bfr[nb][2] };
                        uint32_t b1[2] = { bfr[nb][1], bfr[nb][3] };
                        mma16816(acc[mi][nb * 2 + 0], afr[mi], b0);
                        mma16816(acc[mi][nb * 2 + 1], afr[mi], b1);
                    }
                }
            }
            __syncthreads();   // all warps done with stage s before overwrite
        }

        // ---- epilogue: running max + candidate insert
#pragma unroll
        for (int i = 0; i < 2; i++) {
#pragma unroll
            for (int kk = 0; kk < 2; kk++) {
                int lrow = warp_m * 32 + i * 16 + kk * 8 + g;
                float m = -INFINITY;
#pragma unroll
                for (int j = 0; j < 8; j++) {
                    m = fmaxf(m, acc[i][j][kk * 2 + 0]);
                    m = fmaxf(m, acc[i][j][kk * 2 + 1]);
                }
                atomicMax(&srowmax[lrow], fenc(m));
            }
        }
        __syncthreads();
#pragma unroll
        for (int i = 0; i < 2; i++) {
#pragma unroll
            for (int kk = 0; kk < 2; kk++) {
                int lrow = warp_m * 32 + i * 16 + kk * 8 + g;
                float thr = fdec(srowmax[lrow]) - MARGIN;
                float m = -INFINITY;
#pragma unroll
                for (int j = 0; j < 8; j++) {
                    m = fmaxf(m, acc[i][j][kk * 2 + 0]);
                    m = fmaxf(m, acc[i][j][kk * 2 + 1]);
                }
                if (m < thr) continue;
#pragma unroll
                for (int j = 0; j < 8; j++) {
#pragma unroll
                    for (int h = 0; h < 2; h++) {
                        float v = acc[i][j][kk * 2 + h];
                        if (v >= thr) {
                            int col = nt * 128 + warp_n * 64 + j * 8 + tig * 2 + h;
                            int grow = row0 + lrow;
                            int p = atomicAdd(&g_ccnt[grow], 1);
                            if (p < CAP) g_cand[(size_t)grow * CAP + p] = col;
                        }
                    }
                }
            }
        }
        // next iteration's top-of-loop __syncthreads orders srowmax reuse
    }
}

// -------------------- exact rescore: one warp per row (R8 exact) ------------
__global__ __launch_bounds__(256)
void k_rescore(const float* __restrict__ z) {
    int row = blockIdx.x * 8 + (threadIdx.x >> 5);
    int lane = threadIdx.x & 31;
    int cnt = g_ccnt[row];
    if (cnt > CAP) cnt = CAP;

    float4 zr[8];
    const float4* zp = (const float4*)(z + (size_t)row * D);
#pragma unroll
    for (int i = 0; i < 8; i++) zr[i] = zp[i * 32 + lane];

    float bv = -INFINITY;
    int   bi = 0;
    for (int c = 0; c < cnt; c++) {
        int idx = g_cand[(size_t)row * CAP + c];
        const float4* cp = (const float4*)(g_cbn + (size_t)idx * D);
        float s = 0.0f;
#pragma unroll
        for (int i = 0; i < 8; i++) {
            float4 cv = cp[i * 32 + lane];
            s += zr[i].x * cv.x + zr[i].y * cv.y + zr[i].z * cv.z + zr[i].w * cv.w;
        }
#pragma unroll
        for (int o = 16; o > 0; o >>= 1) s += __shfl_xor_sync(0xFFFFFFFFu, s, o);
        if (s > bv || (s == bv && idx < bi)) { bv = s; bi = idx; }
    }
    if (lane == 0) g_ids[row] = bi;
}

// -------------------- scatter (R8 exact) ------------------------------------
__global__ void k_scatter(const float* __restrict__ z,
                          const float* __restrict__ cb,
                          float* __restrict__ out) {
    __shared__ float red[256];
    int b = blockIdx.x;
    int t = threadIdx.x;
    int id = g_ids[b];

    float4 zv = ((const float4*)(z  + (size_t)b  * D))[t];
    float4 qv = ((const float4*)(cb + (size_t)id * D))[t];

    float4 zq;
    zq.x = zv.x + (qv.x - zv.x);
    zq.y = zv.y + (qv.y - zv.y);
    zq.z = zv.z + (qv.z - zv.z);
    zq.w = zv.w + (qv.w - zv.w);
    ((float4*)(out + OFF_ZQ + (size_t)b * D))[t] = zq;

    float dx = zv.x - qv.x, dy = zv.y - qv.y, dz = zv.z - qv.z, dw = zv.w - qv.w;
    red[t] = dx * dx + dy * dy + dz * dz + dw * dw;

    float* wrow = g_wsum + (size_t)id * D + t * 4;
    atomicAdd(wrow + 0, zv.x);
    atomicAdd(wrow + 1, zv.y);
    atomicAdd(wrow + 2, zv.z);
    atomicAdd(wrow + 3, zv.w);

    __syncthreads();
    for (int s = 128; s > 0; s >>= 1) {
        if (t < s) red[t] += red[t + s];
        __syncthreads();
    }
    if (t == 0) {
        atomicAdd(&g_loss, red[0]);
        atomicAdd(&g_cnt[id], 1.0f);
        out[OFF_IDS + b] = (float)id;
    }
}

// -------------------- final: weight + codebook + count + loss (merged) ------
__global__ void k_final(const float* __restrict__ ema_count,
                        const float* __restrict__ ema_weight,
                        float* __restrict__ out) {
    int64_t i4 = (int64_t)blockIdx.x * blockDim.x + threadIdx.x;
    if (i4 >= (int64_t)K * D / 4) return;
    int row = (int)(i4 >> 8);                    // (i4*4)/1024
    float nc = DECAY * ema_count[row] + ONE_M_D * g_cnt[row];
    if ((i4 & 255) == 0) out[OFF_CNT + row] = nc;
    if (i4 == 0)
        out[OFF_LOSS] = COMMIT * (g_loss / (float)((int64_t)B * D));

    float4 ew = ((const float4*)ema_weight)[i4];
    float4 ws = ((const float4*)g_wsum)[i4];
    float w0 = DECAY * ew.x + ONE_M_D * ws.x;
    float w1 = DECAY * ew.y + ONE_M_D * ws.y;
    float w2 = DECAY * ew.z + ONE_M_D * ws.z;
    float w3 = DECAY * ew.w + ONE_M_D * ws.w;
    int64_t base = i4 * 4;
    out[OFF_W + base + 0] = w0;
    out[OFF_W + base + 1] = w1;
    out[OFF_W + base + 2] = w2;
    out[OFF_W + base + 3] = w3;
    float denom = nc + EPS;
    out[OFF_CB + base + 0] = w0 / denom;
    out[OFF_CB + base + 1] = w1 / denom;
    out[OFF_CB + base + 2] = w2 / denom;
    out[OFF_CB + base + 3] = w3 / denom;
}

// ---------------------------------------------------------------------------
extern "C" void kernel_launch(void* const* d_in, const int* in_sizes, int n_in,
                              void* d_out, int out_size) {
    const float* z          = (const float*)d_in[0];
    const float* codebook   = (const float*)d_in[1];
    const float* ema_count  = (const float*)d_in[2];
    const float* ema_weight = (const float*)d_in[3];
    float* out = (float*)d_out;

    cudaFuncSetAttribute(k_approx, cudaFuncAttributeMaxDynamicSharedMemorySize,
                         DYN_SMEM);

    k_prep<<<4096, 256>>>(z);
    k_norm_cb<<<K, 256>>>(codebook);
    k_approx<<<B / 128, 256, DYN_SMEM>>>(0);
    k_rescore<<<B / 8, 256>>>(z);
    k_scatter<<<B, 256>>>(z, codebook, out);
    k_final<<<(K * D / 4 + 255) / 256, 256>>>(ema_count, ema_weight, out);
}

// round 15
// speedup vs baseline: 1.2229x; 1.0677x over previous
#include <cuda_runtime.h>
#include <cuda_bf16.h>
#include <math.h>
#include <stdint.h>

// Problem constants
#define B  32768
#define K  8192
#define D  1024
#define DECAY   0.99f
#define ONE_M_D 0.01f
#define EPS     1e-5f
#define COMMIT  0.25f
#define NORM_EPS 1e-12f

// Candidate machinery
#define CAP    64
#define MARGIN 0.15f

// Output layout (flattened tuple, float32)
#define OFF_ZQ   0
#define OFF_IDS  (B*D)
#define OFF_LOSS (OFF_IDS + B)
#define OFF_CB   (OFF_LOSS + 1)              // odd -> no float4 stores
#define OFF_CNT  (OFF_CB + K*D)
#define OFF_W    (OFF_CNT + K)               // odd -> no float4 stores

// -------------------- device scratch (no allocation allowed) ----------------
__device__ __align__(16) __nv_bfloat16 g_a0[(size_t)B * D];   // bf16(z)
__device__ __align__(16) __nv_bfloat16 g_b0[(size_t)K * D];   // bf16(cb_norm)
__device__ __align__(16) float g_cbn[(size_t)K * D];          // fp32 cb_norm
__device__ int   g_cand[(size_t)B * CAP];
__device__ int   g_ccnt[B];
__device__ int   g_icnt[K];        // rows per codeword
__device__ int   g_off[K];         // CSR offsets
__device__ int   g_fill[K];        // bucket fill cursors
__device__ int   g_rows[B];        // CSR row lists
__device__ int   g_ids[B];
__device__ float g_loss;

// -------------------- PTX helpers (compute_103-safe) ------------------------
__device__ __forceinline__ uint32_t smem_u32(const void* p) {
    uint32_t a;
    asm("{ .reg .u64 t; cvta.to.shared.u64 t, %1; cvt.u32.u64 %0, t; }"
        : "=r"(a) : "l"(p));
    return a;
}
__device__ __forceinline__ void cp_async16(uint32_t dst, const void* src) {
    asm volatile("cp.async.cg.shared.global [%0], [%1], 16;"
                 :: "r"(dst), "l"(src) : "memory");
}
__device__ __forceinline__ void cp_commit() {
    asm volatile("cp.async.commit_group;" ::: "memory");
}
template <int N> __device__ __forceinline__ void cp_wait() {
    asm volatile("cp.async.wait_group %0;" :: "n"(N) : "memory");
}
__device__ __forceinline__ void ldsm4(uint32_t& r0, uint32_t& r1,
                                      uint32_t& r2, uint32_t& r3, uint32_t a) {
    asm volatile("ldmatrix.sync.aligned.m8n8.x4.shared.b16 {%0,%1,%2,%3}, [%4];"
                 : "=r"(r0), "=r"(r1), "=r"(r2), "=r"(r3) : "r"(a));
}
__device__ __forceinline__ void mma16816(float* c, const uint32_t* a,
                                         const uint32_t* b) {
    asm volatile(
        "mma.sync.aligned.m16n8k16.row.col.f32.bf16.bf16.f32 "
        "{%0,%1,%2,%3}, {%4,%5,%6,%7}, {%8,%9}, {%0,%1,%2,%3};"
        : "+f"(c[0]), "+f"(c[1]), "+f"(c[2]), "+f"(c[3])
        : "r"(a[0]), "r"(a[1]), "r"(a[2]), "r"(a[3]), "r"(b[0]), "r"(b[1]));
}
#define SW128(x) ((x) ^ (((x) >> 3) & 0x70))

// order-preserving float<->uint for atomicMax
__device__ __forceinline__ unsigned fenc(float f) {
    unsigned u = __float_as_uint(f);
    return (u & 0x80000000u) ? ~u : (u | 0x80000000u);
}
__device__ __forceinline__ float fdec(unsigned u) {
    return (u & 0x80000000u) ? __uint_as_float(u ^ 0x80000000u)
                             : __uint_as_float(~u);
}

// -------------------- setup: zero scratch + cast z to bf16 (one pass) -------
__global__ void k_prep(const float* __restrict__ z) {
    int64_t tid = (int64_t)blockIdx.x * blockDim.x + threadIdx.x;
    int64_t stride = (int64_t)gridDim.x * blockDim.x;
    for (int64_t i = tid; i < K; i += stride) { g_icnt[i] = 0; g_fill[i] = 0; }
    for (int64_t i = tid; i < B; i += stride) g_ccnt[i] = 0;
    if (tid == 0) g_loss = 0.0f;
    int64_t n4 = (int64_t)B * D / 4;
    for (int64_t i = tid; i < n4; i += stride) {
        float4 v = ((const float4*)z)[i];
        __nv_bfloat162* p = (__nv_bfloat162*)g_a0 + i * 2;
        __nv_bfloat162 t;
        t.x = __float2bfloat16_rn(v.x); t.y = __float2bfloat16_rn(v.y); p[0] = t;
        t.x = __float2bfloat16_rn(v.z); t.y = __float2bfloat16_rn(v.w); p[1] = t;
    }
}

// normalize codebook rows -> fp32 g_cbn + bf16 g_b0. one block per row.
__global__ void k_norm_cb(const float* __restrict__ cb) {
    __shared__ float red[256];
    int k = blockIdx.x;
    int t = threadIdx.x;
    float4 v = ((const float4*)(cb + (size_t)k * D))[t];
    red[t] = v.x * v.x + v.y * v.y + v.z * v.z + v.w * v.w;
    __syncthreads();
    for (int s = 128; s > 0; s >>= 1) {
        if (t < s) red[t] += red[t + s];
        __syncthreads();
    }
    float denom = fmaxf(sqrtf(red[0]), NORM_EPS);
    float4 o;
    o.x = v.x / denom; o.y = v.y / denom; o.z = v.z / denom; o.w = v.w / denom;
    ((float4*)(g_cbn + (size_t)k * D))[t] = o;
    __nv_bfloat162* p = (__nv_bfloat162*)g_b0 + (size_t)k * (D / 2) + t * 2;
    __nv_bfloat162 x;
    x.x = __float2bfloat16_rn(o.x); x.y = __float2bfloat16_rn(o.y); p[0] = x;
    x.x = __float2bfloat16_rn(o.z); x.y = __float2bfloat16_rn(o.w); p[1] = x;
}

// -------------------- approx bf16 GEMM + candidate harvest (R8 exact) -------
#define DKC   64
#define NDK   (D / DKC)               // 16
#define NT    (K / 128)               // 64
#define TILE_B 16384                  // 128 rows x 128 bytes (64 bf16 cols)
#define STAGE_B (2 * TILE_B)          // A tile + B tile = 32 KB
#define DYN_SMEM (2 * STAGE_B)        // 64 KB

__global__ __launch_bounds__(256, 2)
void k_approx(int dummy) {
    extern __shared__ char dyn[];
    __shared__ unsigned srowmax[128];
    uint32_t sbase = smem_u32(dyn);

    int tid = threadIdx.x;
    int lane = tid & 31;
    int wid = tid >> 5;
    int warp_m = wid >> 1;            // 0..3
    int warp_n = wid & 1;             // 0..1
    int g = lane >> 2;                // 0..7
    int tig = lane & 3;               // 0..3
    int row0 = blockIdx.x * 128;

    int lm_r = lane & 15;
    int lm_c = (lane >> 4) << 4;

    if (tid < 128) srowmax[tid] = 0u;   // < fenc of any float
    __syncthreads();

    const __nv_bfloat16* asrc0 = g_a0 + (size_t)row0 * D;

    for (int nt = 0; nt < NT; nt++) {
        const __nv_bfloat16* bsrc0 = g_b0 + (size_t)nt * 128 * D;

        float acc[2][8][4];
#pragma unroll
        for (int i = 0; i < 2; i++)
#pragma unroll
            for (int j = 0; j < 8; j++)
#pragma unroll
                for (int q = 0; q < 4; q++) acc[i][j][q] = 0.0f;

        // prologue: stage 0 <- dk 0 (A tile + B tile)
        {
            uint32_t sb = sbase;
#pragma unroll
            for (int t2 = 0; t2 < 2; t2++) {
                const __nv_bfloat16* src = t2 ? bsrc0 : asrc0;
#pragma unroll
                for (int it = 0; it < 4; it++) {
                    int c = tid + 256 * it;
                    int r = c >> 3, ch = c & 7;
                    cp_async16(sb + t2 * TILE_B + SW128(r * 128 + ch * 16),
                               src + (size_t)r * D + ch * 8);
                }
            }
            cp_commit();
        }

        for (int dk = 0; dk < NDK; dk++) {
            int s = dk & 1;
            if (dk + 1 < NDK) {
                uint32_t sb = sbase + (s ^ 1) * STAGE_B;
                int koff = (dk + 1) * DKC;
#pragma unroll
                for (int t2 = 0; t2 < 2; t2++) {
                    const __nv_bfloat16* src = (t2 ? bsrc0 : asrc0) + koff;
#pragma unroll
                    for (int it = 0; it < 4; it++) {
                        int c = tid + 256 * it;
                        int r = c >> 3, ch = c & 7;
                        cp_async16(sb + t2 * TILE_B + SW128(r * 128 + ch * 16),
                                   src + (size_t)r * D + ch * 8);
                    }
                }
                cp_commit();
                cp_wait<1>();
            } else {
                cp_wait<0>();
            }
            __syncthreads();

            uint32_t stg = sbase + s * STAGE_B;
#pragma unroll
            for (int step = 0; step < 4; step++) {
                int kc = step * 32 + lm_c;
                uint32_t afr[2][4];
#pragma unroll
                for (int mi = 0; mi < 2; mi++) {
                    int r = warp_m * 32 + mi * 16 + lm_r;
                    ldsm4(afr[mi][0], afr[mi][1], afr[mi][2], afr[mi][3],
                          stg + SW128(r * 128 + kc));
                }
                uint32_t bfr[4][4];
#pragma unroll
                for (int nb = 0; nb < 4; nb++) {
                    int r = warp_n * 64 + nb * 16 + lm_r;
                    ldsm4(bfr[nb][0], bfr[nb][1], bfr[nb][2], bfr[nb][3],
                          stg + TILE_B + SW128(r * 128 + kc));
                }
#pragma unroll
                for (int mi = 0; mi < 2; mi++) {
#pragma unroll
                    for (int nb = 0; nb < 4; nb++) {
                        uint32_t b0[2] = { bfr[nb][0], bfr[nb][2] };
                        uint32_t b1[2] = { bfr[nb][1], bfr[nb][3] };
                        mma16816(acc[mi][nb * 2 + 0], afr[mi], b0);
                        mma16816(acc[mi][nb * 2 + 1], afr[mi], b1);
                    }
                }
            }
            __syncthreads();   // all warps done with stage s before overwrite
        }

        // ---- epilogue: running max + candidate insert
#pragma unroll
        for (int i = 0; i < 2; i++) {
#pragma unroll
            for (int kk = 0; kk < 2; kk++) {
                int lrow = warp_m * 32 + i * 16 + kk * 8 + g;
                float m = -INFINITY;
#pragma unroll
                for (int j = 0; j < 8; j++) {
                    m = fmaxf(m, acc[i][j][kk * 2 + 0]);
                    m = fmaxf(m, acc[i][j][kk * 2 + 1]);
                }
                atomicMax(&srowmax[lrow], fenc(m));
            }
        }
        __syncthreads();
#pragma unroll
        for (int i = 0; i < 2; i++) {
#pragma unroll
            for (int kk = 0; kk < 2; kk++) {
                int lrow = warp_m * 32 + i * 16 + kk * 8 + g;
                float thr = fdec(srowmax[lrow]) - MARGIN;
                float m = -INFINITY;
#pragma unroll
                for (int j = 0; j < 8; j++) {
                    m = fmaxf(m, acc[i][j][kk * 2 + 0]);
                    m = fmaxf(m, acc[i][j][kk * 2 + 1]);
                }
                if (m < thr) continue;
#pragma unroll
                for (int j = 0; j < 8; j++) {
#pragma unroll
                    for (int h = 0; h < 2; h++) {
                        float v = acc[i][j][kk * 2 + h];
                        if (v >= thr) {
                            int col = nt * 128 + warp_n * 64 + j * 8 + tig * 2 + h;
                            int grow = row0 + lrow;
                            int p = atomicAdd(&g_ccnt[grow], 1);
                            if (p < CAP) g_cand[(size_t)grow * CAP + p] = col;
                        }
                    }
                }
            }
        }
        // next iteration's top-of-loop __syncthreads orders srowmax reuse
    }
}

// -------------------- fused rescore + scatter: one warp per row -------------
// Exact fp32 rescore of candidates; then the SAME warp (z already in regs)
// writes z_q, ids, loss partial, and the per-codeword histogram count.
__global__ __launch_bounds__(256)
void k_rescatter(const float* __restrict__ z,
                 const float* __restrict__ cb,
                 float* __restrict__ out) {
    int row = blockIdx.x * 8 + (threadIdx.x >> 5);
    int lane = threadIdx.x & 31;
    int cnt = g_ccnt[row];
    if (cnt > CAP) cnt = CAP;

    float4 zr[8];
    const float4* zp = (const float4*)(z + (size_t)row * D);
#pragma unroll
    for (int i = 0; i < 8; i++) zr[i] = zp[i * 32 + lane];

    float bv = -INFINITY;
    int   bi = 0;
    for (int c = 0; c < cnt; c++) {
        int idx = g_cand[(size_t)row * CAP + c];
        const float4* cp = (const float4*)(g_cbn + (size_t)idx * D);
        float s = 0.0f;
#pragma unroll
        for (int i = 0; i < 8; i++) {
            float4 cv = cp[i * 32 + lane];
            s += zr[i].x * cv.x + zr[i].y * cv.y + zr[i].z * cv.z + zr[i].w * cv.w;
        }
#pragma unroll
        for (int o = 16; o > 0; o >>= 1) s += __shfl_xor_sync(0xFFFFFFFFu, s, o);
        if (s > bv || (s == bv && idx < bi)) { bv = s; bi = idx; }
    }

    // scatter with z still in registers
    const float4* qp = (const float4*)(cb + (size_t)bi * D);
    float4* zqp = (float4*)(out + OFF_ZQ + (size_t)row * D);
    float lsum = 0.0f;
#pragma unroll
    for (int i = 0; i < 8; i++) {
        float4 qv = qp[i * 32 + lane];
        float4 zv = zr[i];
        float4 zq;
        zq.x = zv.x + (qv.x - zv.x);
        zq.y = zv.y + (qv.y - zv.y);
        zq.z = zv.z + (qv.z - zv.z);
        zq.w = zv.w + (qv.w - zv.w);
        zqp[i * 32 + lane] = zq;
        float dx = zv.x - qv.x, dy = zv.y - qv.y;
        float dz = zv.z - qv.z, dw = zv.w - qv.w;
        lsum += dx * dx + dy * dy + dz * dz + dw * dw;
    }
#pragma unroll
    for (int o = 16; o > 0; o >>= 1) lsum += __shfl_xor_sync(0xFFFFFFFFu, lsum, o);
    if (lane == 0) {
        g_ids[row] = bi;
        out[OFF_IDS + row] = (float)bi;
        atomicAdd(&g_loss, lsum);
        atomicAdd(&g_icnt[bi], 1);
    }
}

// -------------------- exclusive prefix sum over g_icnt (1 block) ------------
__global__ void k_prefix() {
    __shared__ int part[256];
    int t = threadIdx.x;
    int base = t * (K / 256);                   // 32 entries each
    int loc[K / 256];
    int s = 0;
#pragma unroll
    for (int i = 0; i < K / 256; i++) { loc[i] = s; s += g_icnt[base + i]; }
    part[t] = s;
    __syncthreads();
    // Hillis-Steele inclusive scan on part[]
    for (int o = 1; o < 256; o <<= 1) {
        int v = (t >= o) ? part[t - o] : 0;
        __syncthreads();
        part[t] += v;
        __syncthreads();
    }
    int off = (t == 0) ? 0 : part[t - 1];
#pragma unroll
    for (int i = 0; i < K / 256; i++) g_off[base + i] = off + loc[i];
}

// -------------------- bucket fill: row indices into CSR lists ---------------
__global__ void k_bucket() {
    int row = blockIdx.x * blockDim.x + threadIdx.x;
    if (row >= B) return;
    int id = g_ids[row];
    int p = atomicAdd(&g_fill[id], 1);
    g_rows[g_off[id] + p] = row;
}

// -------------------- per-codeword gather-sum + final outputs ---------------
// Block per codeword: sum its rows' z vectors (coalesced 4KB reads), then
// new_weight, new_codebook, new_count. No atomics, no g_wsum buffer.
__global__ void k_wfinal(const float* __restrict__ z,
                         const float* __restrict__ ema_count,
                         const float* __restrict__ ema_weight,
                         float* __restrict__ out) {
    int k = blockIdx.x;
    int t = threadIdx.x;
    int cnt = g_icnt[k];
    int off = g_off[k];

    float4 sum = make_float4(0.f, 0.f, 0.f, 0.f);
    for (int r = 0; r < cnt; r++) {
        int row = g_rows[off + r];
        float4 v = ((const float4*)(z + (size_t)row * D))[t];
        sum.x += v.x; sum.y += v.y; sum.z += v.z; sum.w += v.w;
    }

    float nc = DECAY * ema_count[k] + ONE_M_D * (float)cnt;
    float4 ew = ((const float4*)(ema_weight + (size_t)k * D))[t];
    float w0 = DECAY * ew.x + ONE_M_D * sum.x;
    float w1 = DECAY * ew.y + ONE_M_D * sum.y;
    float w2 = DECAY * ew.z + ONE_M_D * sum.z;
    float w3 = DECAY * ew.w + ONE_M_D * sum.w;
    int64_t base = (int64_t)k * D + t * 4;
    out[OFF_W + base + 0] = w0;
    out[OFF_W + base + 1] = w1;
    out[OFF_W + base + 2] = w2;
    out[OFF_W + base + 3] = w3;
    float denom = nc + EPS;
    out[OFF_CB + base + 0] = w0 / denom;
    out[OFF_CB + base + 1] = w1 / denom;
    out[OFF_CB + base + 2] = w2 / denom;
    out[OFF_CB + base + 3] = w3 / denom;
    if (t == 0) out[OFF_CNT + k] = nc;
    if (k == 0 && t == 0)
        out[OFF_LOSS] = COMMIT * (g_loss / (float)((int64_t)B * D));
}

// ---------------------------------------------------------------------------
extern "C" void kernel_launch(void* const* d_in, const int* in_sizes, int n_in,
                              void* d_out, int out_size) {
    const float* z          = (const float*)d_in[0];
    const float* codebook   = (const float*)d_in[1];
    const float* ema_count  = (const float*)d_in[2];
    const float* ema_weight = (const float*)d_in[3];
    float* out = (float*)d_out;

    cudaFuncSetAttribute(k_approx, cudaFuncAttributeMaxDynamicSharedMemorySize,
                         DYN_SMEM);

    k_prep<<<4096, 256>>>(z);
    k_norm_cb<<<K, 256>>>(codebook);
    k_approx<<<B / 128, 256, DYN_SMEM>>>(0);
    k_rescatter<<<B / 8, 256>>>(z, codebook, out);
    k_prefix<<<1, 256>>>();
    k_bucket<<<B / 256, 256>>>();
    k_wfinal<<<K, 256>>>(z, ema_count, ema_weight, out);
}

// round 17
// speedup vs baseline: 1.3143x; 1.0747x over previous
#include <cuda_runtime.h>
#include <cuda_bf16.h>
#include <math.h>
#include <stdint.h>

// Problem constants
#define B  32768
#define K  8192
#define D  1024
#define DECAY   0.99f
#define ONE_M_D 0.01f
#define EPS     1e-5f
#define COMMIT  0.25f
#define NORM_EPS 1e-12f

// Candidate machinery
#define CAP    64
#define MARGIN 0.15f

// Output layout (flattened tuple, float32)
#define OFF_ZQ   0
#define OFF_IDS  (B*D)
#define OFF_LOSS (OFF_IDS + B)
#define OFF_CB   (OFF_LOSS + 1)              // odd -> no float4 stores
#define OFF_CNT  (OFF_CB + K*D)
#define OFF_W    (OFF_CNT + K)               // odd -> no float4 stores

// -------------------- device scratch (no allocation allowed) ----------------
__device__ __align__(16) __nv_bfloat16 g_a0[(size_t)B * D];   // bf16(z)
__device__ __align__(16) __nv_bfloat16 g_b0[(size_t)K * D];   // bf16(cb_norm)
__device__ __align__(16) float g_cbn[(size_t)K * D];          // fp32 cb_norm
__device__ int   g_cand[(size_t)B * CAP];
__device__ int   g_ccnt[B];
__device__ int   g_icnt[K];        // rows per codeword
__device__ int   g_off[K];         // CSR offsets
__device__ int   g_fill[K];        // bucket fill cursors
__device__ int   g_rows[B];        // CSR row lists
__device__ int   g_ids[B];
__device__ float g_loss;

// -------------------- PTX helpers (compute_103-safe) ------------------------
__device__ __forceinline__ uint32_t smem_u32(const void* p) {
    uint32_t a;
    asm("{ .reg .u64 t; cvta.to.shared.u64 t, %1; cvt.u32.u64 %0, t; }"
        : "=r"(a) : "l"(p));
    return a;
}
__device__ __forceinline__ void cp_async16(uint32_t dst, const void* src) {
    asm volatile("cp.async.cg.shared.global [%0], [%1], 16;"
                 :: "r"(dst), "l"(src) : "memory");
}
__device__ __forceinline__ void cp_commit() {
    asm volatile("cp.async.commit_group;" ::: "memory");
}
template <int N> __device__ __forceinline__ void cp_wait() {
    asm volatile("cp.async.wait_group %0;" :: "n"(N) : "memory");
}
__device__ __forceinline__ void ldsm4(uint32_t& r0, uint32_t& r1,
                                      uint32_t& r2, uint32_t& r3, uint32_t a) {
    asm volatile("ldmatrix.sync.aligned.m8n8.x4.shared.b16 {%0,%1,%2,%3}, [%4];"
                 : "=r"(r0), "=r"(r1), "=r"(r2), "=r"(r3) : "r"(a));
}
__device__ __forceinline__ void mma16816(float* c, const uint32_t* a,
                                         const uint32_t* b) {
    asm volatile(
        "mma.sync.aligned.m16n8k16.row.col.f32.bf16.bf16.f32 "
        "{%0,%1,%2,%3}, {%4,%5,%6,%7}, {%8,%9}, {%0,%1,%2,%3};"
        : "+f"(c[0]), "+f"(c[1]), "+f"(c[2]), "+f"(c[3])
        : "r"(a[0]), "r"(a[1]), "r"(a[2]), "r"(a[3]), "r"(b[0]), "r"(b[1]));
}
#define SW128(x) ((x) ^ (((x) >> 3) & 0x70))

// order-preserving float<->uint for atomicMax
__device__ __forceinline__ unsigned fenc(float f) {
    unsigned u = __float_as_uint(f);
    return (u & 0x80000000u) ? ~u : (u | 0x80000000u);
}
__device__ __forceinline__ float fdec(unsigned u) {
    return (u & 0x80000000u) ? __uint_as_float(u ^ 0x80000000u)
                             : __uint_as_float(~u);
}

// -------------------- merged setup: cb-norm (blocks < K) + prep -------------
__global__ void k_setup(const float* __restrict__ z,
                        const float* __restrict__ cb) {
    if (blockIdx.x < K) {
        __shared__ float red[256];
        int k = blockIdx.x;
        int t = threadIdx.x;
        float4 v = ((const float4*)(cb + (size_t)k * D))[t];
        red[t] = v.x * v.x + v.y * v.y + v.z * v.z + v.w * v.w;
        __syncthreads();
        for (int s = 128; s > 0; s >>= 1) {
            if (t < s) red[t] += red[t + s];
            __syncthreads();
        }
        float denom = fmaxf(sqrtf(red[0]), NORM_EPS);
        float4 o;
        o.x = v.x / denom; o.y = v.y / denom;
        o.z = v.z / denom; o.w = v.w / denom;
        ((float4*)(g_cbn + (size_t)k * D))[t] = o;
        __nv_bfloat162* p = (__nv_bfloat162*)g_b0 + (size_t)k * (D / 2) + t * 2;
        __nv_bfloat162 x;
        x.x = __float2bfloat16_rn(o.x); x.y = __float2bfloat16_rn(o.y); p[0] = x;
        x.x = __float2bfloat16_rn(o.z); x.y = __float2bfloat16_rn(o.w); p[1] = x;
    } else {
        int64_t blk = blockIdx.x - K;               // 0..4095
        int64_t tid = blk * blockDim.x + threadIdx.x;
        int64_t stride = (int64_t)4096 * blockDim.x;
        for (int64_t i = tid; i < K; i += stride) { g_icnt[i] = 0; g_fill[i] = 0; }
        for (int64_t i = tid; i < B; i += stride) g_ccnt[i] = 0;
        if (tid == 0) g_loss = 0.0f;
        int64_t n4 = (int64_t)B * D / 4;
        for (int64_t i = tid; i < n4; i += stride) {
            float4 v = ((const float4*)z)[i];
            __nv_bfloat162* p = (__nv_bfloat162*)g_a0 + i * 2;
            __nv_bfloat162 t2;
            t2.x = __float2bfloat16_rn(v.x); t2.y = __float2bfloat16_rn(v.y);
            p[0] = t2;
            t2.x = __float2bfloat16_rn(v.z); t2.y = __float2bfloat16_rn(v.w);
            p[1] = t2;
        }
    }
}

// -------------------- approx bf16 GEMM + candidate harvest ------------------
// Unit u = (row-block rb = u>>6, n-tile nt = u&63), 16384 units. 304 CTAs
// (152 SMs x occ 2) statically take contiguous unit ranges -> per-SM work is
// uniform (kills the 256-CTA wave-quantization tail). Chunk stream c=u*16+dk
// over a 3-stage cp.async pipeline; warp tiles identical to R8.
#define NW    304
#define UNITS (256 * 64)              // 16384
#define DKC   64
#define NDK   16
#define TILE_B 16384                  // 128 rows x 128 bytes (64 bf16 cols)
#define STAGE_B (2 * TILE_B)          // 32 KB
#define STAGES 3
#define DYN_SMEM (STAGES * STAGE_B)   // 96 KB

__device__ __forceinline__ void load_chunk(uint32_t sbase, int c, int tid) {
    int u = c >> 4;
    int dk = c & 15;
    int rb = u >> 6;
    int nt = u & 63;
    uint32_t sb = sbase + (c % STAGES) * STAGE_B;
    const __nv_bfloat16* a = g_a0 + (size_t)rb * 128 * D + dk * DKC;
    const __nv_bfloat16* b = g_b0 + (size_t)nt * 128 * D + dk * DKC;
#pragma unroll
    for (int it = 0; it < 4; it++) {
        int cc = tid + 256 * it;
        int r = cc >> 3, ch = cc & 7;
        cp_async16(sb + SW128(r * 128 + ch * 16), a + (size_t)r * D + ch * 8);
    }
#pragma unroll
    for (int it = 0; it < 4; it++) {
        int cc = tid + 256 * it;
        int r = cc >> 3, ch = cc & 7;
        cp_async16(sb + TILE_B + SW128(r * 128 + ch * 16),
                   b + (size_t)r * D + ch * 8);
    }
    cp_commit();
}

__global__ __launch_bounds__(256, 2)
void k_approx(int dummy) {
    extern __shared__ char dyn[];
    __shared__ unsigned srowmax[128];
    uint32_t sbase = smem_u32(dyn);

    int tid = threadIdx.x;
    int lane = tid & 31;
    int wid = tid >> 5;
    int warp_m = wid >> 1;            // 0..3
    int warp_n = wid & 1;             // 0..1
    int g = lane >> 2;                // 0..7
    int tig = lane & 3;               // 0..3

    int lm_r = lane & 15;
    int lm_c = (lane >> 4) << 4;

    int u0 = (int)((int64_t)blockIdx.x * UNITS / NW);
    int u1 = (int)((int64_t)(blockIdx.x + 1) * UNITS / NW);
    if (u0 >= u1) return;
    int c0 = u0 * 16, c1 = u1 * 16;

    int cur_rb = -1;

    load_chunk(sbase, c0, tid);
    if (c0 + 1 < c1) load_chunk(sbase, c0 + 1, tid);

    for (int u = u0; u < u1; u++) {
        int rb = u >> 6;
        int nt = u & 63;
        if (rb != cur_rb) {
            __syncthreads();                 // all done with previous srowmax
            if (tid < 128) srowmax[tid] = 0u;
            cur_rb = rb;
            // subsequent dk-loop __syncthreads orders this write before use
        }

        float acc[2][8][4];
#pragma unroll
        for (int i = 0; i < 2; i++)
#pragma unroll
            for (int j = 0; j < 8; j++)
#pragma unroll
                for (int q = 0; q < 4; q++) acc[i][j][q] = 0.0f;

        for (int dk = 0; dk < NDK; dk++) {
            int c = u * 16 + dk;
            if (c == c1 - 1) cp_wait<0>(); else cp_wait<1>();
            __syncthreads();

            uint32_t stg = sbase + (c % STAGES) * STAGE_B;
#pragma unroll
            for (int step = 0; step < 4; step++) {
                int kc = step * 32 + lm_c;
                uint32_t afr[2][4];
#pragma unroll
                for (int mi = 0; mi < 2; mi++) {
                    int r = warp_m * 32 + mi * 16 + lm_r;
                    ldsm4(afr[mi][0], afr[mi][1], afr[mi][2], afr[mi][3],
                          stg + SW128(r * 128 + kc));
                }
                uint32_t bfr[4][4];
#pragma unroll
                for (int nb = 0; nb < 4; nb++) {
                    int r = warp_n * 64 + nb * 16 + lm_r;
                    ldsm4(bfr[nb][0], bfr[nb][1], bfr[nb][2], bfr[nb][3],
                          stg + TILE_B + SW128(r * 128 + kc));
                }
#pragma unroll
                for (int mi = 0; mi < 2; mi++) {
#pragma unroll
                    for (int nb = 0; nb < 4; nb++) {
                        uint32_t b0[2] = { bfr[nb][0], bfr[nb][2] };
                        uint32_t b1[2] = { bfr[nb][1], bfr[nb][3] };
                        mma16816(acc[mi][nb * 2 + 0], afr[mi], b0);
                        mma16816(acc[mi][nb * 2 + 1], afr[mi], b1);
                    }
                }
            }
            if (c + 2 < c1) load_chunk(sbase, c + 2, tid);
        }

        // ---- epilogue: running max + candidate insert (rows rb*128+..)
#pragma unroll
        for (int i = 0; i < 2; i++) {
#pragma unroll
            for (int kk = 0; kk < 2; kk++) {
                int lrow = warp_m * 32 + i * 16 + kk * 8 + g;
                float m = -INFINITY;
#pragma unroll
                for (int j = 0; j < 8; j++) {
                    m = fmaxf(m, acc[i][j][kk * 2 + 0]);
                    m = fmaxf(m, acc[i][j][kk * 2 + 1]);
                }
                atomicMax(&srowmax[lrow], fenc(m));
            }
        }
        __syncthreads();
#pragma unroll
        for (int i = 0; i < 2; i++) {
#pragma unroll
            for (int kk = 0; kk < 2; kk++) {
                int lrow = warp_m * 32 + i * 16 + kk * 8 + g;
                float thr = fdec(srowmax[lrow]) - MARGIN;
                float m = -INFINITY;
#pragma unroll
                for (int j = 0; j < 8; j++) {
                    m = fmaxf(m, acc[i][j][kk * 2 + 0]);
                    m = fmaxf(m, acc[i][j][kk * 2 + 1]);
                }
                if (m < thr) continue;
#pragma unroll
                for (int j = 0; j < 8; j++) {
#pragma unroll
                    for (int h = 0; h < 2; h++) {
                        float v = acc[i][j][kk * 2 + h];
                        if (v >= thr) {
                            int col = nt * 128 + warp_n * 64 + j * 8 + tig * 2 + h;
                            int grow = rb * 128 + lrow;
                            int p = atomicAdd(&g_ccnt[grow], 1);
                            if (p < CAP) g_cand[(size_t)grow * CAP + p] = col;
                        }
                    }
                }
            }
        }
        // next u's dk-loop __syncthreads (or rb-change sync) orders reuse
    }
}

// -------------------- fused rescore + scatter: one warp per row -------------
__global__ __launch_bounds__(256)
void k_rescatter(const float* __restrict__ z,
                 const float* __restrict__ cb,
                 float* __restrict__ out) {
    int row = blockIdx.x * 8 + (threadIdx.x >> 5);
    int lane = threadIdx.x & 31;
    int cnt = g_ccnt[row];
    if (cnt > CAP) cnt = CAP;

    float4 zr[8];
    const float4* zp = (const float4*)(z + (size_t)row * D);
#pragma unroll
    for (int i = 0; i < 8; i++) zr[i] = zp[i * 32 + lane];

    float bv = -INFINITY;
    int   bi = 0;
    for (int c = 0; c < cnt; c++) {
        int idx = g_cand[(size_t)row * CAP + c];
        const float4* cp = (const float4*)(g_cbn + (size_t)idx * D);
        float s = 0.0f;
#pragma unroll
        for (int i = 0; i < 8; i++) {
            float4 cv = cp[i * 32 + lane];
            s += zr[i].x * cv.x + zr[i].y * cv.y + zr[i].z * cv.z + zr[i].w * cv.w;
        }
#pragma unroll
        for (int o = 16; o > 0; o >>= 1) s += __shfl_xor_sync(0xFFFFFFFFu, s, o);
        if (s > bv || (s == bv && idx < bi)) { bv = s; bi = idx; }
    }

    const float4* qp = (const float4*)(cb + (size_t)bi * D);
    float4* zqp = (float4*)(out + OFF_ZQ + (size_t)row * D);
    float lsum = 0.0f;
#pragma unroll
    for (int i = 0; i < 8; i++) {
        float4 qv = qp[i * 32 + lane];
        float4 zv = zr[i];
        float4 zq;
        zq.x = zv.x + (qv.x - zv.x);
        zq.y = zv.y + (qv.y - zv.y);
        zq.z = zv.z + (qv.z - zv.z);
        zq.w = zv.w + (qv.w - zv.w);
        zqp[i * 32 + lane] = zq;
        float dx = zv.x - qv.x, dy = zv.y - qv.y;
        float dz = zv.z - qv.z, dw = zv.w - qv.w;
        lsum += dx * dx + dy * dy + dz * dz + dw * dw;
    }
#pragma unroll
    for (int o = 16; o > 0; o >>= 1) lsum += __shfl_xor_sync(0xFFFFFFFFu, lsum, o);
    if (lane == 0) {
        g_ids[row] = bi;
        out[OFF_IDS + row] = (float)bi;
        atomicAdd(&g_loss, lsum);
        atomicAdd(&g_icnt[bi], 1);
    }
}

// -------------------- exclusive prefix sum over g_icnt (1 block) ------------
__global__ void k_prefix() {
    __shared__ int part[256];
    int t = threadIdx.x;
    int base = t * (K / 256);
    int loc[K / 256];
    int s = 0;
#pragma unroll
    for (int i = 0; i < K / 256; i++) { loc[i] = s; s += g_icnt[base + i]; }
    part[t] = s;
    __syncthreads();
    for (int o = 1; o < 256; o <<= 1) {
        int v = (t >= o) ? part[t - o] : 0;
        __syncthreads();
        part[t] += v;
        __syncthreads();
    }
    int off = (t == 0) ? 0 : part[t - 1];
#pragma unroll
    for (int i = 0; i < K / 256; i++) g_off[base + i] = off + loc[i];
}

// -------------------- bucket fill: row indices into CSR lists ---------------
__global__ void k_bucket() {
    int row = blockIdx.x * blockDim.x + threadIdx.x;
    if (row >= B) return;
    int id = g_ids[row];
    int p = atomicAdd(&g_fill[id], 1);
    g_rows[g_off[id] + p] = row;
}

// -------------------- per-codeword gather-sum + final outputs ---------------
__global__ void k_wfinal(const float* __restrict__ z,
                         const float* __restrict__ ema_count,
                         const float* __restrict__ ema_weight,
                         float* __restrict__ out) {
    int k = blockIdx.x;
    int t = threadIdx.x;
    int cnt = g_icnt[k];
    int off = g_off[k];

    float4 sum = make_float4(0.f, 0.f, 0.f, 0.f);
    for (int r = 0; r < cnt; r++) {
        int row = g_rows[off + r];
        float4 v = ((const float4*)(z + (size_t)row * D))[t];
        sum.x += v.x; sum.y += v.y; sum.z += v.z; sum.w += v.w;
    }

    float nc = DECAY * ema_count[k] + ONE_M_D * (float)cnt;
    float4 ew = ((const float4*)(ema_weight + (size_t)k * D))[t];
    float w0 = DECAY * ew.x + ONE_M_D * sum.x;
    float w1 = DECAY * ew.y + ONE_M_D * sum.y;
    float w2 = DECAY * ew.z + ONE_M_D * sum.z;
    float w3 = DECAY * ew.w + ONE_M_D * sum.w;
    int64_t base = (int64_t)k * D + t * 4;
    out[OFF_W + base + 0] = w0;
    out[OFF_W + base + 1] = w1;
    out[OFF_W + base + 2] = w2;
    out[OFF_W + base + 3] = w3;
    float denom = nc + EPS;
    out[OFF_CB + base + 0] = w0 / denom;
    out[OFF_CB + base + 1] = w1 / denom;
    out[OFF_CB + base + 2] = w2 / denom;
    out[OFF_CB + base + 3] = w3 / denom;
    if (t == 0) out[OFF_CNT + k] = nc;
    if (k == 0 && t == 0)
        out[OFF_LOSS] = COMMIT * (g_loss / (float)((int64_t)B * D));
}

// ---------------------------------------------------------------------------
extern "C" void kernel_launch(void* const* d_in, const int* in_sizes, int n_in,
                              void* d_out, int out_size) {
    const float* z          = (const float*)d_in[0];
    const float* codebook   = (const float*)d_in[1];
    const float* ema_count  = (const float*)d_in[2];
    const float* ema_weight = (const float*)d_in[3];
    float* out = (float*)d_out;

    cudaFuncSetAttribute(k_approx, cudaFuncAttributeMaxDynamicSharedMemorySize,
                         DYN_SMEM);

    k_setup<<<K + 4096, 256>>>(z, codebook);
    k_approx<<<NW, 256, DYN_SMEM>>>(0);
    k_rescatter<<<B / 8, 256>>>(z, codebook, out);
    k_prefix<<<1, 256>>>();
    k_bucket<<<B / 256, 256>>>();
    k_wfinal<<<K, 256>>>(z, ema_count, ema_weight, out);
}